// round 4
// baseline (speedup 1.0000x reference)
#include <cuda_runtime.h>
#include <cuda_bf16.h>

// Quantum convolution: B=32, Cin=8, Cout=16, H=W=32, K=3, NQ=3, DRC=3, IT=30.
// 3-qubit statevector sim per (b, cout, cin, pixel); reduce over cin.
//
// R4 (= R3 resubmit after infra failure): packed f32x2 gate application (FFMA2),
// sparse scalar layer 0 from |000>, CNOT rings folded into pack order (layer 0)
// and measurement signs (layer 2).
//
// State packing: Y0=(a0,a1), Y1=(a2,a3), Y2=(a4,a5), Y3=(a6,a7), real/imag split.
// Wire 0 (stride 4): packed pairs (Y0,Y2),(Y1,Y3). Wire 1: (Y0,Y1),(Y2,Y3).
// Wire 2 (stride 1): within-register via hi/lo swap + mixed packs.

#define N_B    32
#define N_CIN  8
#define N_COUT 16
#define N_IT   30
#define N_HW   32
#define N_PIX  (N_IT * N_IT)       // 900
#define N_LQ   9

#define ROT_STRIDE 76              // padded per-cin stride (floats)
#define IP_STRIDE  12

typedef unsigned long long u64;

__device__ __forceinline__ u64 f2pk(float lo, float hi) {
    u64 r; asm("mov.b64 %0, {%1, %2};" : "=l"(r) : "f"(lo), "f"(hi)); return r;
}
__device__ __forceinline__ u64 f2dup(float x) { return f2pk(x, x); }
__device__ __forceinline__ void f2unpk(u64 x, float& lo, float& hi) {
    asm("mov.b64 {%0, %1}, %2;" : "=f"(lo), "=f"(hi) : "l"(x));
}
__device__ __forceinline__ u64 f2swap(u64 x) {
    u64 r;
    asm("{\n\t.reg .b32 lo, hi;\n\tmov.b64 {lo, hi}, %1;\n\tmov.b64 %0, {hi, lo};\n\t}"
        : "=l"(r) : "l"(x));
    return r;
}
__device__ __forceinline__ u64 f2mul(u64 a, u64 b) {
    u64 d; asm("mul.rn.f32x2 %0, %1, %2;" : "=l"(d) : "l"(a), "l"(b)); return d;
}
__device__ __forceinline__ u64 f2fma(u64 a, u64 b, u64 c) {
    u64 d; asm("fma.rn.f32x2 %0, %1, %2, %3;" : "=l"(d) : "l"(a), "l"(b), "l"(c)); return d;
}

// Precomputed Rot matrices: [cout][cin][lq][8: u00r,u00i,u01r,u01i,u10r,u10i,u11r,u11i]
__device__ float g_rot[N_COUT * N_CIN * N_LQ * 8];

__global__ void prep_rot_kernel(const float* __restrict__ w) {
    int t = blockIdx.x * blockDim.x + threadIdx.x;
    if (t >= N_COUT * N_CIN * N_LQ) return;
    const float* wp = w + t * 3;
    float phi = wp[0], th = wp[1], om = wp[2];
    float c, s, cp, sp, cm, sm;
    __sincosf(0.5f * th,         &s,  &c);
    __sincosf(0.5f * (phi + om), &sp, &cp);
    __sincosf(0.5f * (phi - om), &sm, &cm);
    float* o = g_rot + t * 8;
    o[0] =  cp * c;  o[1] = -sp * c;
    o[2] = -cm * s;  o[3] = -sm * s;
    o[4] =  cm * s;  o[5] = -sm * s;
    o[6] =  cp * c;  o[7] =  sp * c;
}

#define TILES ((N_PIX + 31) / 32)   // 29

// Fused gate G = Rot * RY(theta) for gate index g; declares G00r..G11i, c, s.
#define FUSE_GATE(g) \
    float th_ = x[g] * prm[g]; float c, s; __sincosf(th_, &s, &c); \
    const float4* m4_ = reinterpret_cast<const float4*>(rm + (g) * 8); \
    float4 m0_ = m4_[0], m1_ = m4_[1]; \
    float G00r = m0_.x * c + m0_.z * s, G00i = m0_.y * c + m0_.w * s; \
    float G01r = m0_.z * c - m0_.x * s, G01i = m0_.w * c - m0_.y * s; \
    float G10r = m1_.x * c + m1_.z * s, G10i = m1_.y * c + m1_.w * s; \
    float G11r = m1_.z * c - m1_.x * s, G11i = m1_.w * c - m1_.y * s;

// Duplicated packs for wire-0/1 gates.
#define GATE_DUPS \
    u64 d00r = f2dup(G00r), d01r = f2dup(G01r), d10r = f2dup(G10r), d11r = f2dup(G11r); \
    u64 d00i = f2dup(G00i), d01i = f2dup(G01i), d10i = f2dup(G10i), d11i = f2dup(G11i); \
    u64 n00i = f2dup(-G00i), n01i = f2dup(-G01i), n10i = f2dup(-G10i), n11i = f2dup(-G11i);

// Apply gate to packed pair (X = "0" role, Z = "1" role).
#define PAIR_APPLY(Xr, Xi, Zr, Zi) do { \
    u64 _xr = f2fma(d00r, Xr, f2fma(n00i, Xi, f2fma(d01r, Zr, f2mul(n01i, Zi)))); \
    u64 _xi = f2fma(d00r, Xi, f2fma(d00i, Xr, f2fma(d01r, Zi, f2mul(d01i, Zr)))); \
    u64 _zr = f2fma(d10r, Xr, f2fma(n10i, Xi, f2fma(d11r, Zr, f2mul(n11i, Zi)))); \
    u64 _zi = f2fma(d10r, Xi, f2fma(d10i, Xr, f2fma(d11r, Zi, f2mul(d11i, Zr)))); \
    Xr = _xr; Xi = _xi; Zr = _zr; Zi = _zi; } while (0)

// Wire-2 (within-register) gate.
#define W2_DUPS \
    u64 Ar  = f2pk(G00r,  G11r), Cr  = f2pk(G01r,  G10r); \
    u64 Ai  = f2pk(G00i,  G11i), Ci  = f2pk(G01i,  G10i); \
    u64 nAi = f2pk(-G00i, -G11i), nCi = f2pk(-G01i, -G10i);

#define W2_APPLY(Yr, Yi) do { \
    u64 _sr = f2swap(Yr), _si = f2swap(Yi); \
    u64 _nr = f2fma(Ar, Yr, f2fma(Cr, _sr, f2fma(nAi, Yi, f2mul(nCi, _si)))); \
    u64 _ni = f2fma(Ar, Yi, f2fma(Cr, _si, f2fma(Ai, Yr, f2mul(Ci, _sr)))); \
    Yr = _nr; Yi = _ni; } while (0)

#define HI_EXCHANGE(A_, B_) do { \
    float _al, _ah, _bl, _bh; f2unpk(A_, _al, _ah); f2unpk(B_, _bl, _bh); \
    A_ = f2pk(_al, _bh); B_ = f2pk(_bl, _ah); } while (0)

__global__ void __launch_bounds__(256, 3)
qconv_kernel(const float* __restrict__ inp,   // (32,8,32,32)
             const float* __restrict__ ip,    // (16,8,3,3)
             float* __restrict__ out)         // (32,16,30,30)
{
    __shared__ float s_ip[N_CIN * IP_STRIDE];
    __shared__ __align__(16) float s_rot[N_CIN * ROT_STRIDE];

    int bid  = blockIdx.x;
    int tile = bid % TILES;
    int bc   = bid / TILES;
    int cout = bc % N_COUT;
    int b    = bc / N_COUT;
    int tid  = threadIdx.x;

    for (int i = tid; i < N_CIN * N_LQ; i += 256) {
        int ci = i / N_LQ, j = i % N_LQ;
        s_ip[ci * IP_STRIDE + j] = 0.5f * ip[cout * (N_CIN * N_LQ) + i];
    }
    for (int i = tid; i < N_CIN * N_LQ * 8; i += 256) {
        int ci = i / (N_LQ * 8), j = i % (N_LQ * 8);
        s_rot[ci * ROT_STRIDE + j] = g_rot[cout * (N_CIN * N_LQ * 8) + i];
    }
    __syncthreads();

    int cin = tid & 7;
    int p   = tile * 32 + (tid >> 3);
    bool valid = (p < N_PIX);
    if (!valid) p = N_PIX - 1;
    int ii = p / N_IT, jj = p % N_IT;

    const float* xp = inp + ((b * N_CIN + cin) * N_HW + ii) * N_HW + jj;
    float x[9];
#pragma unroll
    for (int l = 0; l < 3; l++)
#pragma unroll
        for (int q = 0; q < 3; q++)
            x[l * 3 + q] = __ldg(xp + l * N_HW + q);

    const float* prm = s_ip  + cin * IP_STRIDE;
    const float* rm  = s_rot + cin * ROT_STRIDE;

    // ---------- Layer 0: sparse scalar from |000> ----------
    float b0r, b0i, b4r, b4i;
    {
        float th_ = x[0] * prm[0]; float c, s; __sincosf(th_, &s, &c);
        const float4* m4_ = reinterpret_cast<const float4*>(rm);
        float4 m0_ = m4_[0], m1_ = m4_[1];
        b0r = m0_.x * c + m0_.z * s;  b0i = m0_.y * c + m0_.w * s;
        b4r = m1_.x * c + m1_.z * s;  b4i = m1_.y * c + m1_.w * s;
    }
    float a0r, a0i, a2r, a2i, a4r, a4i, a6r, a6i;
    {
        float th_ = x[1] * prm[1]; float c, s; __sincosf(th_, &s, &c);
        const float4* m4_ = reinterpret_cast<const float4*>(rm + 8);
        float4 m0_ = m4_[0], m1_ = m4_[1];
        float H00r = m0_.x * c + m0_.z * s, H00i = m0_.y * c + m0_.w * s;
        float H10r = m1_.x * c + m1_.z * s, H10i = m1_.y * c + m1_.w * s;
        a0r = H00r * b0r - H00i * b0i;  a0i = H00r * b0i + H00i * b0r;
        a2r = H10r * b0r - H10i * b0i;  a2i = H10r * b0i + H10i * b0r;
        a4r = H00r * b4r - H00i * b4i;  a4i = H00r * b4i + H00i * b4r;
        a6r = H10r * b4r - H10i * b4i;  a6i = H10r * b4i + H10i * b4r;
    }
    float c0r,c0i,c1r,c1i,c2r,c2i,c3r,c3i,c4r,c4i,c5r,c5i,c6r,c6i,c7r,c7i;
    {
        float th_ = x[2] * prm[2]; float c, s; __sincosf(th_, &s, &c);
        const float4* m4_ = reinterpret_cast<const float4*>(rm + 16);
        float4 m0_ = m4_[0], m1_ = m4_[1];
        float K00r = m0_.x * c + m0_.z * s, K00i = m0_.y * c + m0_.w * s;
        float K10r = m1_.x * c + m1_.z * s, K10i = m1_.y * c + m1_.w * s;
        c0r = K00r*a0r - K00i*a0i;  c0i = K00r*a0i + K00i*a0r;
        c1r = K10r*a0r - K10i*a0i;  c1i = K10r*a0i + K10i*a0r;
        c2r = K00r*a2r - K00i*a2i;  c2i = K00r*a2i + K00i*a2r;
        c3r = K10r*a2r - K10i*a2i;  c3i = K10r*a2i + K10i*a2r;
        c4r = K00r*a4r - K00i*a4i;  c4i = K00r*a4i + K00i*a4r;
        c5r = K10r*a4r - K10i*a4i;  c5i = K10r*a4i + K10i*a4r;
        c6r = K00r*a6r - K00i*a6i;  c6i = K00r*a6i + K00i*a6r;
        c7r = K10r*a6r - K10i*a6i;  c7i = K10r*a6i + K10i*a6r;
    }
    // Layer-0 CNOT ring folded into the pack: slots hold [c0, c7, c3, c4, c6, c1, c5, c2]
    u64 Y0r = f2pk(c0r, c7r), Y0i = f2pk(c0i, c7i);
    u64 Y1r = f2pk(c3r, c4r), Y1i = f2pk(c3i, c4i);
    u64 Y2r = f2pk(c6r, c1r), Y2i = f2pk(c6i, c1i);
    u64 Y3r = f2pk(c5r, c2r), Y3i = f2pk(c5i, c2i);

    // ---------- Layer 1 (packed) ----------
    { FUSE_GATE(3); GATE_DUPS;
      PAIR_APPLY(Y0r, Y0i, Y2r, Y2i); PAIR_APPLY(Y1r, Y1i, Y3r, Y3i); }
    { FUSE_GATE(4); GATE_DUPS;
      PAIR_APPLY(Y0r, Y0i, Y1r, Y1i); PAIR_APPLY(Y2r, Y2i, Y3r, Y3i); }
    { FUSE_GATE(5); W2_DUPS;
      W2_APPLY(Y0r, Y0i); W2_APPLY(Y1r, Y1i); W2_APPLY(Y2r, Y2i); W2_APPLY(Y3r, Y3i); }

    // Explicit packed CNOT ring after layer 1.
    { u64 t;
      t = Y2r; Y2r = Y3r; Y3r = t;   // swap slots (4,6),(5,7)
      t = Y2i; Y2i = Y3i; Y3i = t;
      Y1r = f2swap(Y1r); Y1i = f2swap(Y1i);   // swap (2,3)
      Y3r = f2swap(Y3r); Y3i = f2swap(Y3i);   // swap (6,7)
      HI_EXCHANGE(Y0r, Y2r); HI_EXCHANGE(Y0i, Y2i);   // swap (1,5)
      HI_EXCHANGE(Y1r, Y3r); HI_EXCHANGE(Y1i, Y3i);   // swap (3,7)
    }

    // ---------- Layer 2 (packed); final CNOT folded into measurement signs ----------
    { FUSE_GATE(6); GATE_DUPS;
      PAIR_APPLY(Y0r, Y0i, Y2r, Y2i); PAIR_APPLY(Y1r, Y1i, Y3r, Y3i); }
    { FUSE_GATE(7); GATE_DUPS;
      PAIR_APPLY(Y0r, Y0i, Y1r, Y1i); PAIR_APPLY(Y2r, Y2i, Y3r, Y3i); }
    { FUSE_GATE(8); W2_DUPS;
      W2_APPLY(Y0r, Y0i); W2_APPLY(Y1r, Y1i); W2_APPLY(Y2r, Y2i); W2_APPLY(Y3r, Y3i); }

    // Measurement: sign(j) = + iff popcount(j) even (final CNOT folded in).
    u64 accA = f2mul(Y0r, Y0r);
    accA = f2fma(Y0i, Y0i, accA);
    accA = f2fma(Y3r, Y3r, accA);
    accA = f2fma(Y3i, Y3i, accA);
    u64 accB = f2mul(Y1r, Y1r);
    accB = f2fma(Y1i, Y1i, accB);
    accB = f2fma(Y2r, Y2r, accB);
    accB = f2fma(Y2i, Y2i, accB);
    float aAl, aAh, aBl, aBh;
    f2unpk(accA, aAl, aAh);
    f2unpk(accB, aBl, aBh);
    float e = (aAl + aBh) - (aAh + aBl);

    // reduce over cin (8 consecutive lanes)
    e += __shfl_xor_sync(0xFFFFFFFFu, e, 1);
    e += __shfl_xor_sync(0xFFFFFFFFu, e, 2);
    e += __shfl_xor_sync(0xFFFFFFFFu, e, 4);

    if (valid && cin == 0)
        out[(b * N_COUT + cout) * N_PIX + p] = e;
}

extern "C" void kernel_launch(void* const* d_in, const int* in_sizes, int n_in,
                              void* d_out, int out_size) {
    const float* inputs       = (const float*)d_in[0];  // (32,8,32,32)
    const float* input_params = (const float*)d_in[1];  // (16,8,3,3)
    const float* weights      = (const float*)d_in[2];  // (16,8,3,3,3)
    float* out = (float*)d_out;                         // (32,16,30,30)

    prep_rot_kernel<<<(N_COUT * N_CIN * N_LQ + 255) / 256, 256>>>(weights);

    int grid = N_B * N_COUT * TILES;   // 14848
    qconv_kernel<<<grid, 256>>>(inputs, input_params, out);
}

// round 9
// speedup vs baseline: 1.6390x; 1.6390x over previous
#include <cuda_runtime.h>
#include <cuda_bf16.h>

// Quantum convolution: B=32, Cin=8, Cout=16, H=W=32, K=3, NQ=3, DRC=3, IT=30.
// 3-qubit statevector sim per (b, cout, cin, pixel); reduce over cin.
//
// R9 (= R5..R8 resubmit after broker capacity timeouts): scalar math,
// SU(2)-compressed gates (store/fuse only u00,u01; G10=-conj(G01),
// G11=conj(G00)), sparse layer 0 from |000>, CNOT rings folded:
// layer-0 ring = register relabel, final ring = measurement signs.

#define N_B    32
#define N_CIN  8
#define N_COUT 16
#define N_IT   30
#define N_HW   32
#define N_PIX  (N_IT * N_IT)       // 900
#define N_LQ   9

#define GATE_STRIDE 36             // 9 gates * 4 floats; cin*36 mod 32 = 4*cin -> conflict-free float4
#define IP_STRIDE   12

// Compressed Rot: [cout][cin][lq][4: u00r,u00i,u01r,u01i]
__device__ float g_rot[N_COUT * N_CIN * N_LQ * 4];

__global__ void prep_rot_kernel(const float* __restrict__ w) {
    int t = blockIdx.x * blockDim.x + threadIdx.x;
    if (t >= N_COUT * N_CIN * N_LQ) return;
    const float* wp = w + t * 3;
    float phi = wp[0], th = wp[1], om = wp[2];
    float c, s, cp, sp, cm, sm;
    __sincosf(0.5f * th,         &s,  &c);
    __sincosf(0.5f * (phi + om), &sp, &cp);
    __sincosf(0.5f * (phi - om), &sm, &cm);
    float* o = g_rot + t * 4;
    o[0] =  cp * c;  o[1] = -sp * c;   // u00
    o[2] = -cm * s;  o[3] = -sm * s;   // u01
}

#define TILES ((N_PIX + 31) / 32)   // 29

#define SWAP_AMP(i, j) { float _t = sr[i]; sr[i] = sr[j]; sr[j] = _t; \
                         _t = si[i]; si[i] = si[j]; si[j] = _t; }

// Fuse gate g: G00=(ar,ai), G01=(br,bi); G10=-conj(G01), G11=conj(G00) implied.
#define FUSE_GATE(g, ar, ai, br, bi) \
    float ar, ai, br, bi; \
    { float th_ = x[g] * prm[g]; float c_, s_; __sincosf(th_, &s_, &c_); \
      float4 m_ = *reinterpret_cast<const float4*>(rm + (g) * 4); \
      ar = m_.x * c_ + m_.z * s_;  ai = m_.y * c_ + m_.w * s_; \
      br = m_.z * c_ - m_.x * s_;  bi = m_.w * c_ - m_.y * s_; }

// SU(2) pair apply: (x0,x1) -> (a x0 + b x1, -conj(b) x0 + conj(a) x1)
#define PAIR_APPLY(ar, ai, br, bi, i0, i1) { \
    float x0r = sr[i0], x0i = si[i0], x1r = sr[i1], x1i = si[i1]; \
    sr[i0] = ar * x0r - ai * x0i + br * x1r - bi * x1i; \
    si[i0] = ar * x0i + ai * x0r + br * x1i + bi * x1r; \
    sr[i1] = ar * x1r + ai * x1i - br * x0r - bi * x0i; \
    si[i1] = ar * x1i - ai * x1r - br * x0i + bi * x0r; }

__global__ void __launch_bounds__(256, 4)
qconv_kernel(const float* __restrict__ inp,   // (32,8,32,32)
             const float* __restrict__ ip,    // (16,8,3,3)
             float* __restrict__ out)         // (32,16,30,30)
{
    __shared__ float s_ip[N_CIN * IP_STRIDE];                   // 96 floats
    __shared__ __align__(16) float s_gate[N_CIN * GATE_STRIDE]; // 288 floats

    int bid  = blockIdx.x;
    int tile = bid % TILES;
    int bc   = bid / TILES;
    int cout = bc % N_COUT;
    int b    = bc / N_COUT;
    int tid  = threadIdx.x;

    for (int i = tid; i < N_CIN * N_LQ; i += 256) {
        int ci = i / N_LQ, j = i % N_LQ;
        s_ip[ci * IP_STRIDE + j] = 0.5f * ip[cout * (N_CIN * N_LQ) + i];
    }
    for (int i = tid; i < N_CIN * N_LQ * 4; i += 256) {
        int ci = i / (N_LQ * 4), j = i % (N_LQ * 4);
        s_gate[ci * GATE_STRIDE + j] = g_rot[cout * (N_CIN * N_LQ * 4) + i];
    }
    __syncthreads();

    int cin = tid & 7;
    int p   = tile * 32 + (tid >> 3);
    bool valid = (p < N_PIX);
    if (!valid) p = N_PIX - 1;   // clamp: reads stay in-bounds, no write
    int ii = p / N_IT, jj = p % N_IT;

    const float* xp = inp + ((b * N_CIN + cin) * N_HW + ii) * N_HW + jj;
    float x[9];
#pragma unroll
    for (int l = 0; l < 3; l++)
#pragma unroll
        for (int q = 0; q < 3; q++)
            x[l * 3 + q] = __ldg(xp + l * N_HW + q);

    const float* prm = s_ip   + cin * IP_STRIDE;
    const float* rm  = s_gate + cin * GATE_STRIDE;

    float sr[8], si[8];

    // ---------- Layer 0: sparse from |000> ----------
    {
        FUSE_GATE(0, a0r, a0i, b0r, b0i);
        // after wire-0 gate: amp0 = G00 = a0, amp4 = G10 = -conj(b0)
        float p0r = a0r,  p0i = a0i;
        float p4r = -b0r, p4i = b0i;

        FUSE_GATE(1, a1r, a1i, b1r, b1i);
        // pairs (0,2),(4,6): second input zero -> out = col0 * amp
        float d0r = a1r * p0r - a1i * p0i,  d0i = a1r * p0i + a1i * p0r;
        float d2r = -b1r * p0r - b1i * p0i, d2i = -b1r * p0i + b1i * p0r;
        float d4r = a1r * p4r - a1i * p4i,  d4i = a1r * p4i + a1i * p4r;
        float d6r = -b1r * p4r - b1i * p4i, d6i = -b1r * p4i + b1i * p4r;

        FUSE_GATE(2, a2r, a2i, b2r, b2i);
        float c0r = a2r * d0r - a2i * d0i,  c0i = a2r * d0i + a2i * d0r;
        float c1r = -b2r * d0r - b2i * d0i, c1i = -b2r * d0i + b2i * d0r;
        float c2r = a2r * d2r - a2i * d2i,  c2i = a2r * d2i + a2i * d2r;
        float c3r = -b2r * d2r - b2i * d2i, c3i = -b2r * d2i + b2i * d2r;
        float c4r = a2r * d4r - a2i * d4i,  c4i = a2r * d4i + a2i * d4r;
        float c5r = -b2r * d4r - b2i * d4i, c5i = -b2r * d4i + b2i * d4r;
        float c6r = a2r * d6r - a2i * d6i,  c6i = a2r * d6i + a2i * d6r;
        float c7r = -b2r * d6r - b2i * d6i, c7i = -b2r * d6i + b2i * d6r;

        // layer-0 CNOT ring folded into relabel: s[i] = c[t[i]], t=[0,7,3,4,6,1,5,2]
        sr[0] = c0r; si[0] = c0i;   sr[1] = c7r; si[1] = c7i;
        sr[2] = c3r; si[2] = c3i;   sr[3] = c4r; si[3] = c4i;
        sr[4] = c6r; si[4] = c6i;   sr[5] = c1r; si[5] = c1i;
        sr[6] = c5r; si[6] = c5i;   sr[7] = c2r; si[7] = c2i;
    }

    // ---------- Layer 1 ----------
    {
        FUSE_GATE(3, ar, ai, br, bi);   // wire 0, stride 4
        PAIR_APPLY(ar, ai, br, bi, 0, 4); PAIR_APPLY(ar, ai, br, bi, 1, 5);
        PAIR_APPLY(ar, ai, br, bi, 2, 6); PAIR_APPLY(ar, ai, br, bi, 3, 7);
    }
    {
        FUSE_GATE(4, ar, ai, br, bi);   // wire 1, stride 2
        PAIR_APPLY(ar, ai, br, bi, 0, 2); PAIR_APPLY(ar, ai, br, bi, 1, 3);
        PAIR_APPLY(ar, ai, br, bi, 4, 6); PAIR_APPLY(ar, ai, br, bi, 5, 7);
    }
    {
        FUSE_GATE(5, ar, ai, br, bi);   // wire 2, stride 1
        PAIR_APPLY(ar, ai, br, bi, 0, 1); PAIR_APPLY(ar, ai, br, bi, 2, 3);
        PAIR_APPLY(ar, ai, br, bi, 4, 5); PAIR_APPLY(ar, ai, br, bi, 6, 7);
    }
    // mid CNOT ring (register renames, free)
    SWAP_AMP(4, 6); SWAP_AMP(5, 7);
    SWAP_AMP(2, 3); SWAP_AMP(6, 7);
    SWAP_AMP(1, 5); SWAP_AMP(3, 7);

    // ---------- Layer 2 (final CNOT ring folded into measurement signs) ----------
    {
        FUSE_GATE(6, ar, ai, br, bi);
        PAIR_APPLY(ar, ai, br, bi, 0, 4); PAIR_APPLY(ar, ai, br, bi, 1, 5);
        PAIR_APPLY(ar, ai, br, bi, 2, 6); PAIR_APPLY(ar, ai, br, bi, 3, 7);
    }
    {
        FUSE_GATE(7, ar, ai, br, bi);
        PAIR_APPLY(ar, ai, br, bi, 0, 2); PAIR_APPLY(ar, ai, br, bi, 1, 3);
        PAIR_APPLY(ar, ai, br, bi, 4, 6); PAIR_APPLY(ar, ai, br, bi, 5, 7);
    }
    {
        FUSE_GATE(8, ar, ai, br, bi);
        PAIR_APPLY(ar, ai, br, bi, 0, 1); PAIR_APPLY(ar, ai, br, bi, 2, 3);
        PAIR_APPLY(ar, ai, br, bi, 4, 5); PAIR_APPLY(ar, ai, br, bi, 6, 7);
    }

    // measurement: sign(j) = + iff popcount(j) even  (positives: 0,3,5,6)
    float pp = sr[0] * sr[0] + si[0] * si[0];
    pp += sr[3] * sr[3] + si[3] * si[3];
    pp += sr[5] * sr[5] + si[5] * si[5];
    pp += sr[6] * sr[6] + si[6] * si[6];
    float nn = sr[1] * sr[1] + si[1] * si[1];
    nn += sr[2] * sr[2] + si[2] * si[2];
    nn += sr[4] * sr[4] + si[4] * si[4];
    nn += sr[7] * sr[7] + si[7] * si[7];
    float e = pp - nn;

    // reduce over cin (8 consecutive lanes)
    e += __shfl_xor_sync(0xFFFFFFFFu, e, 1);
    e += __shfl_xor_sync(0xFFFFFFFFu, e, 2);
    e += __shfl_xor_sync(0xFFFFFFFFu, e, 4);

    if (valid && cin == 0)
        out[(b * N_COUT + cout) * N_PIX + p] = e;
}

extern "C" void kernel_launch(void* const* d_in, const int* in_sizes, int n_in,
                              void* d_out, int out_size) {
    const float* inputs       = (const float*)d_in[0];  // (32,8,32,32)
    const float* input_params = (const float*)d_in[1];  // (16,8,3,3)
    const float* weights      = (const float*)d_in[2];  // (16,8,3,3,3)
    float* out = (float*)d_out;                         // (32,16,30,30)

    prep_rot_kernel<<<(N_COUT * N_CIN * N_LQ + 255) / 256, 256>>>(weights);

    int grid = N_B * N_COUT * TILES;   // 14848
    qconv_kernel<<<grid, 256>>>(inputs, input_params, out);
}

// round 10
// speedup vs baseline: 1.8564x; 1.1326x over previous
#include <cuda_runtime.h>
#include <cuda_bf16.h>

// Quantum convolution: B=32, Cin=8, Cout=16, H=W=32, K=3, NQ=3, DRC=3, IT=30.
// 3-qubit statevector sim per (b, cout, cin, pixel); reduce over cin.
//
// R10: transposed mapping — warp = cin, lane = pixel. Coalesced input loads
// (~2-3 lines/warp vs 32), broadcast gate LDS, coalesced output. cin-reduction
// via smem (bank-conflict-free). Core circuit identical to R9 (SU(2)-compressed
// gates, sparse layer 0, folded CNOT rings).

#define N_B    32
#define N_CIN  8
#define N_COUT 16
#define N_IT   30
#define N_HW   32
#define N_PIX  (N_IT * N_IT)       // 900
#define N_LQ   9

#define GATE_STRIDE 36             // 9 gates * 4 floats (+broadcast anyway)
#define IP_STRIDE   12

// Compressed Rot: [cout][cin][lq][4: u00r,u00i,u01r,u01i]
__device__ float g_rot[N_COUT * N_CIN * N_LQ * 4];

__global__ void prep_rot_kernel(const float* __restrict__ w) {
    int t = blockIdx.x * blockDim.x + threadIdx.x;
    if (t >= N_COUT * N_CIN * N_LQ) return;
    const float* wp = w + t * 3;
    float phi = wp[0], th = wp[1], om = wp[2];
    float c, s, cp, sp, cm, sm;
    __sincosf(0.5f * th,         &s,  &c);
    __sincosf(0.5f * (phi + om), &sp, &cp);
    __sincosf(0.5f * (phi - om), &sm, &cm);
    float* o = g_rot + t * 4;
    o[0] =  cp * c;  o[1] = -sp * c;   // u00
    o[2] = -cm * s;  o[3] = -sm * s;   // u01
}

#define TILES ((N_PIX + 31) / 32)   // 29

#define SWAP_AMP(i, j) { float _t = sr[i]; sr[i] = sr[j]; sr[j] = _t; \
                         _t = si[i]; si[i] = si[j]; si[j] = _t; }

// Fuse gate g: G00=(ar,ai), G01=(br,bi); G10=-conj(G01), G11=conj(G00) implied.
#define FUSE_GATE(g, ar, ai, br, bi) \
    float ar, ai, br, bi; \
    { float th_ = x[g] * prm[g]; float c_, s_; __sincosf(th_, &s_, &c_); \
      float4 m_ = *reinterpret_cast<const float4*>(rm + (g) * 4); \
      ar = m_.x * c_ + m_.z * s_;  ai = m_.y * c_ + m_.w * s_; \
      br = m_.z * c_ - m_.x * s_;  bi = m_.w * c_ - m_.y * s_; }

// SU(2) pair apply: (x0,x1) -> (a x0 + b x1, -conj(b) x0 + conj(a) x1)
#define PAIR_APPLY(ar, ai, br, bi, i0, i1) { \
    float x0r = sr[i0], x0i = si[i0], x1r = sr[i1], x1i = si[i1]; \
    sr[i0] = ar * x0r - ai * x0i + br * x1r - bi * x1i; \
    si[i0] = ar * x0i + ai * x0r + br * x1i + bi * x1r; \
    sr[i1] = ar * x1r + ai * x1i - br * x0r - bi * x0i; \
    si[i1] = ar * x1i - ai * x1r - br * x0i + bi * x0r; }

__global__ void __launch_bounds__(256, 4)
qconv_kernel(const float* __restrict__ inp,   // (32,8,32,32)
             const float* __restrict__ ip,    // (16,8,3,3)
             float* __restrict__ out)         // (32,16,30,30)
{
    __shared__ float s_ip[N_CIN * IP_STRIDE];                   // 96 floats
    __shared__ __align__(16) float s_gate[N_CIN * GATE_STRIDE]; // 288 floats
    __shared__ float s_red[256];

    int bid  = blockIdx.x;
    int tile = bid % TILES;
    int bc   = bid / TILES;
    int cout = bc % N_COUT;
    int b    = bc / N_COUT;
    int tid  = threadIdx.x;

    for (int i = tid; i < N_CIN * N_LQ; i += 256) {
        int ci = i / N_LQ, j = i % N_LQ;
        s_ip[ci * IP_STRIDE + j] = 0.5f * ip[cout * (N_CIN * N_LQ) + i];
    }
    for (int i = tid; i < N_CIN * N_LQ * 4; i += 256) {
        int ci = i / (N_LQ * 4), j = i % (N_LQ * 4);
        s_gate[ci * GATE_STRIDE + j] = g_rot[cout * (N_CIN * N_LQ * 4) + i];
    }
    __syncthreads();

    // Transposed mapping: warp = cin, lane = pixel within the 32-pixel tile.
    int cin  = tid >> 5;
    int lane = tid & 31;
    int p    = tile * 32 + lane;
    bool valid = (p < N_PIX);
    int pc = valid ? p : (N_PIX - 1);   // clamp reads only
    int ii = pc / N_IT, jj = pc % N_IT;

    // Coalesced input loads: lanes have consecutive p -> contiguous runs.
    const float* xp = inp + ((b * N_CIN + cin) * N_HW + ii) * N_HW + jj;
    float x[9];
#pragma unroll
    for (int l = 0; l < 3; l++)
#pragma unroll
        for (int q = 0; q < 3; q++)
            x[l * 3 + q] = __ldg(xp + l * N_HW + q);

    // Warp-uniform (broadcast) shared pointers.
    const float* prm = s_ip   + cin * IP_STRIDE;
    const float* rm  = s_gate + cin * GATE_STRIDE;

    float sr[8], si[8];

    // ---------- Layer 0: sparse from |000> ----------
    {
        FUSE_GATE(0, a0r, a0i, b0r, b0i);
        float p0r = a0r,  p0i = a0i;
        float p4r = -b0r, p4i = b0i;

        FUSE_GATE(1, a1r, a1i, b1r, b1i);
        float d0r = a1r * p0r - a1i * p0i,  d0i = a1r * p0i + a1i * p0r;
        float d2r = -b1r * p0r - b1i * p0i, d2i = -b1r * p0i + b1i * p0r;
        float d4r = a1r * p4r - a1i * p4i,  d4i = a1r * p4i + a1i * p4r;
        float d6r = -b1r * p4r - b1i * p4i, d6i = -b1r * p4i + b1i * p4r;

        FUSE_GATE(2, a2r, a2i, b2r, b2i);
        float c0r = a2r * d0r - a2i * d0i,  c0i = a2r * d0i + a2i * d0r;
        float c1r = -b2r * d0r - b2i * d0i, c1i = -b2r * d0i + b2i * d0r;
        float c2r = a2r * d2r - a2i * d2i,  c2i = a2r * d2i + a2i * d2r;
        float c3r = -b2r * d2r - b2i * d2i, c3i = -b2r * d2i + b2i * d2r;
        float c4r = a2r * d4r - a2i * d4i,  c4i = a2r * d4i + a2i * d4r;
        float c5r = -b2r * d4r - b2i * d4i, c5i = -b2r * d4i + b2i * d4r;
        float c6r = a2r * d6r - a2i * d6i,  c6i = a2r * d6i + a2i * d6r;
        float c7r = -b2r * d6r - b2i * d6i, c7i = -b2r * d6i + b2i * d6r;

        // layer-0 CNOT ring folded: s[i] = c[t[i]], t=[0,7,3,4,6,1,5,2]
        sr[0] = c0r; si[0] = c0i;   sr[1] = c7r; si[1] = c7i;
        sr[2] = c3r; si[2] = c3i;   sr[3] = c4r; si[3] = c4i;
        sr[4] = c6r; si[4] = c6i;   sr[5] = c1r; si[5] = c1i;
        sr[6] = c5r; si[6] = c5i;   sr[7] = c2r; si[7] = c2i;
    }

    // ---------- Layer 1 ----------
    {
        FUSE_GATE(3, ar, ai, br, bi);   // wire 0, stride 4
        PAIR_APPLY(ar, ai, br, bi, 0, 4); PAIR_APPLY(ar, ai, br, bi, 1, 5);
        PAIR_APPLY(ar, ai, br, bi, 2, 6); PAIR_APPLY(ar, ai, br, bi, 3, 7);
    }
    {
        FUSE_GATE(4, ar, ai, br, bi);   // wire 1, stride 2
        PAIR_APPLY(ar, ai, br, bi, 0, 2); PAIR_APPLY(ar, ai, br, bi, 1, 3);
        PAIR_APPLY(ar, ai, br, bi, 4, 6); PAIR_APPLY(ar, ai, br, bi, 5, 7);
    }
    {
        FUSE_GATE(5, ar, ai, br, bi);   // wire 2, stride 1
        PAIR_APPLY(ar, ai, br, bi, 0, 1); PAIR_APPLY(ar, ai, br, bi, 2, 3);
        PAIR_APPLY(ar, ai, br, bi, 4, 5); PAIR_APPLY(ar, ai, br, bi, 6, 7);
    }
    // mid CNOT ring (register renames, free)
    SWAP_AMP(4, 6); SWAP_AMP(5, 7);
    SWAP_AMP(2, 3); SWAP_AMP(6, 7);
    SWAP_AMP(1, 5); SWAP_AMP(3, 7);

    // ---------- Layer 2 (final CNOT ring folded into measurement signs) ----------
    {
        FUSE_GATE(6, ar, ai, br, bi);
        PAIR_APPLY(ar, ai, br, bi, 0, 4); PAIR_APPLY(ar, ai, br, bi, 1, 5);
        PAIR_APPLY(ar, ai, br, bi, 2, 6); PAIR_APPLY(ar, ai, br, bi, 3, 7);
    }
    {
        FUSE_GATE(7, ar, ai, br, bi);
        PAIR_APPLY(ar, ai, br, bi, 0, 2); PAIR_APPLY(ar, ai, br, bi, 1, 3);
        PAIR_APPLY(ar, ai, br, bi, 4, 6); PAIR_APPLY(ar, ai, br, bi, 5, 7);
    }
    {
        FUSE_GATE(8, ar, ai, br, bi);
        PAIR_APPLY(ar, ai, br, bi, 0, 1); PAIR_APPLY(ar, ai, br, bi, 2, 3);
        PAIR_APPLY(ar, ai, br, bi, 4, 5); PAIR_APPLY(ar, ai, br, bi, 6, 7);
    }

    // measurement: sign(j) = + iff popcount(j) even  (positives: 0,3,5,6)
    float pp = sr[0] * sr[0] + si[0] * si[0];
    pp += sr[3] * sr[3] + si[3] * si[3];
    pp += sr[5] * sr[5] + si[5] * si[5];
    pp += sr[6] * sr[6] + si[6] * si[6];
    float nn = sr[1] * sr[1] + si[1] * si[1];
    nn += sr[2] * sr[2] + si[2] * si[2];
    nn += sr[4] * sr[4] + si[4] * si[4];
    nn += sr[7] * sr[7] + si[7] * si[7];
    float e = pp - nn;

    // cin-reduction via smem: s_red[cin*32 + lane]; bank = lane -> conflict-free.
    s_red[tid] = e;
    __syncthreads();

    if (tid < 32) {
        float acc = 0.0f;
#pragma unroll
        for (int w = 0; w < N_CIN; w++)
            acc += s_red[w * 32 + tid];
        int po = tile * 32 + tid;
        if (po < N_PIX)
            out[(b * N_COUT + cout) * N_PIX + po] = acc;   // coalesced
    }
}

extern "C" void kernel_launch(void* const* d_in, const int* in_sizes, int n_in,
                              void* d_out, int out_size) {
    const float* inputs       = (const float*)d_in[0];  // (32,8,32,32)
    const float* input_params = (const float*)d_in[1];  // (16,8,3,3)
    const float* weights      = (const float*)d_in[2];  // (16,8,3,3,3)
    float* out = (float*)d_out;                         // (32,16,30,30)

    prep_rot_kernel<<<(N_COUT * N_CIN * N_LQ + 255) / 256, 256>>>(weights);

    int grid = N_B * N_COUT * TILES;   // 14848
    qconv_kernel<<<grid, 256>>>(inputs, input_params, out);
}